// round 5
// baseline (speedup 1.0000x reference)
#include <cuda_runtime.h>
#include <cstdint>

#define N_NODES 4096
#define FEAT    32
#define G3      192
#define HDIM    64
#define BATCH   4
#define TSTEPS  8
#define NBT     (BATCH*TSTEPS)           // 32
#define MAXD    128
#define NROWS   (NBT*N_NODES)            // 131072

// ---- gru mma kernel geometry ----
#define NP      64                        // nodes per block
#define GT      256                       // threads (8 warps: 2 M x 4 N)
#define DS_STRIDE 264                     // Ds row stride (256 cols + pad)

// smem float offsets
#define O_AH    0                         // A frags hi  [12 k8][4 m16][32][4]
#define O_AL    6144
#define O_BH    12288                     // B frags hi  [12 k8][24 n8][32][2]
#define O_BL    30720
#define O_DS    49152                     // [16][264]
#define O_BIAS  53376                     // [256]
#define O_WD    53632                     // [64]
#define SM_FLOATS 53696                   // 214784 bytes

// -------- static device scratch --------
__device__ int   g_row_len[N_NODES];
__device__ float g_row_wsum[N_NODES];
__device__ int2  g_ell_cv[N_NODES * MAXD];
__device__ float g_bnA[FEAT];
__device__ float g_bnC[FEAT];
__device__ float g_Wcomb[FEAT * G3];
__device__ float g_bcomb[G3];
__device__ float g_partN[N_NODES * 64];
__device__ float g_xT[(size_t)N_NODES * NBT * FEAT];
__device__ float g_ya[(size_t)NROWS * FEAT];

// ============================================================
// helpers
// ============================================================
__device__ __forceinline__ uint32_t tf32_rna(float v) {
    uint32_t b;
    asm("cvt.rna.tf32.f32 %0, %1;" : "=r"(b) : "f"(v));
    return b;
}
__device__ __forceinline__ void tf32_split(float v, uint32_t& hi, uint32_t& lo) {
    hi = tf32_rna(v);
    lo = tf32_rna(v - __uint_as_float(hi));
}
__device__ __forceinline__ float sigm(float v) { return 1.0f / (1.0f + __expf(-v)); }

__device__ __forceinline__ void mma8(float* d, const uint4& a, const uint2& b) {
    asm volatile(
        "mma.sync.aligned.m16n8k8.row.col.f32.tf32.tf32.f32 "
        "{%0,%1,%2,%3}, {%4,%5,%6,%7}, {%8,%9}, {%0,%1,%2,%3};"
        : "+f"(d[0]), "+f"(d[1]), "+f"(d[2]), "+f"(d[3])
        : "r"(a.x), "r"(a.y), "r"(a.z), "r"(a.w), "r"(b.x), "r"(b.y));
}

// ============================================================
// Kernel 1: dense adj -> packed ELL (deterministic ballot order)
// ============================================================
__global__ void build_ell_kernel(const float* __restrict__ adj)
{
    const int warp = (blockIdx.x * blockDim.x + threadIdx.x) >> 5;
    const int lane = threadIdx.x & 31;
    const float* row = adj + (size_t)warp * N_NODES;
    const int base = warp * MAXD;
    int cnt = 0; float wsum = 0.f;
    for (int i = 0; i < N_NODES / 32; ++i) {
        const int c = i * 32 + lane;
        const float v = row[c];
        wsum += v;
        const unsigned mask = __ballot_sync(0xffffffffu, v != 0.0f);
        if (v != 0.0f) {
            const int pos = cnt + __popc(mask & ((1u << lane) - 1u));
            if (pos < MAXD) g_ell_cv[base + pos] = make_int2(c, __float_as_int(v));
        }
        cnt += __popc(mask);
    }
    #pragma unroll
    for (int o = 16; o > 0; o >>= 1) wsum += __shfl_xor_sync(0xffffffffu, wsum, o);
    if (lane == 0) {
        g_row_len[warp]  = cnt < MAXD ? cnt : MAXD;
        g_row_wsum[warp] = wsum;
    }
}

// ============================================================
// Kernel 2: transpose x + per-node BN partials
// ============================================================
__global__ void __launch_bounds__(256)
transpose_bn_kernel(const float* __restrict__ x)
{
    const int n   = blockIdx.x;
    const int tid = threadIdx.x;
    const int bt  = tid >> 3;
    const int f0  = (tid & 7) * 4;
    const int lane = tid & 31;
    const int w    = tid >> 5;

    const float4 v = *(const float4*)(x + ((size_t)bt * N_NODES + n) * FEAT + f0);
    *(float4*)(g_xT + (size_t)n * (NBT * FEAT) + bt * FEAT + f0) = v;

    float s0 = v.x, s1 = v.y, s2 = v.z, s3 = v.w;
    float q0 = v.x * v.x, q1 = v.y * v.y, q2 = v.z * v.z, q3 = v.w * v.w;
    #pragma unroll
    for (int o = 8; o <= 16; o <<= 1) {
        s0 += __shfl_xor_sync(0xffffffffu, s0, o);
        s1 += __shfl_xor_sync(0xffffffffu, s1, o);
        s2 += __shfl_xor_sync(0xffffffffu, s2, o);
        s3 += __shfl_xor_sync(0xffffffffu, s3, o);
        q0 += __shfl_xor_sync(0xffffffffu, q0, o);
        q1 += __shfl_xor_sync(0xffffffffu, q1, o);
        q2 += __shfl_xor_sync(0xffffffffu, q2, o);
        q3 += __shfl_xor_sync(0xffffffffu, q3, o);
    }
    __shared__ float sh[8][64];
    if (lane < 8) {
        sh[w][f0 + 0]      = s0;  sh[w][f0 + 1]      = s1;
        sh[w][f0 + 2]      = s2;  sh[w][f0 + 3]      = s3;
        sh[w][32 + f0 + 0] = q0;  sh[w][32 + f0 + 1] = q1;
        sh[w][32 + f0 + 2] = q2;  sh[w][32 + f0 + 3] = q3;
    }
    __syncthreads();
    if (tid < 64) {
        float a = 0.f;
        #pragma unroll
        for (int i = 0; i < 8; ++i) a += sh[i][tid];
        g_partN[n * 64 + tid] = a;
    }
}

// ============================================================
// Kernel 3: finalize BN affine + Wcomb/bcomb
// ============================================================
__global__ void __launch_bounds__(256)
finalize_kernel(const float* __restrict__ gamma,
                const float* __restrict__ beta,
                const float* __restrict__ Wgcn,
                const float* __restrict__ bgcn,
                const float* __restrict__ Wih,
                const float* __restrict__ bih)
{
    __shared__ float red[4][64];
    __shared__ float s_sum[32], s_sq[32];
    const int tid = threadIdx.x;
    {
        float a = 0.f;
        const int c = tid & 63;
        for (int n = tid >> 6; n < N_NODES; n += 4) a += g_partN[n * 64 + c];
        red[tid >> 6][c] = a;
    }
    __syncthreads();
    if (tid < 64) {
        const float a = red[0][tid] + red[1][tid] + red[2][tid] + red[3][tid];
        if (tid < 32) s_sum[tid] = a; else s_sq[tid - 32] = a;
    }
    __syncthreads();
    if (tid < 32) {
        const float M    = (float)NROWS;
        const float mean = s_sum[tid] / M;
        const float var  = s_sq[tid] / M - mean * mean;
        const float aK   = gamma[tid] * (1.0f / sqrtf(var + 1e-5f));
        g_bnA[tid] = aK;
        g_bnC[tid] = beta[tid] - mean * aK;
    }
    for (int idx = tid; idx < FEAT * G3; idx += blockDim.x) {
        const int f = idx / G3, j = idx % G3;
        float acc = 0.f;
        #pragma unroll 8
        for (int c = 0; c < 32; ++c) acc += Wgcn[f * 32 + c] * Wih[c * G3 + j];
        g_Wcomb[idx] = acc;
    }
    if (tid < G3) {
        float acc = bih[tid];
        #pragma unroll 8
        for (int c = 0; c < 32; ++c) acc += bgcn[c] * Wih[c * G3 + tid];
        g_bcomb[tid] = acc;
    }
}

// ============================================================
// Kernel 4: aggregation (one block = one node, all 32 bt)
// ============================================================
__global__ void __launch_bounds__(256)
agg_kernel()
{
    const int m   = blockIdx.x;
    const int tid = threadIdx.x;
    const int f   = tid & 31;
    const int bt0 = tid >> 5;

    const int len = g_row_len[m];
    const float wsum = g_row_wsum[m];
    const int2* cv = g_ell_cv + m * MAXD;

    float a0 = 0.f, a1 = 0.f, a2 = 0.f, a3 = 0.f;
    const int off = bt0 * FEAT + f;

    int k = 0;
    for (; k + 1 < len; k += 2) {
        const int2 e0 = cv[k], e1 = cv[k + 1];
        const float w0 = __int_as_float(e0.y), w1 = __int_as_float(e1.y);
        const float* p0 = g_xT + (size_t)e0.x * (NBT * FEAT) + off;
        const float* p1 = g_xT + (size_t)e1.x * (NBT * FEAT) + off;
        const float v00 = p0[0],    v01 = p0[256],  v02 = p0[512],  v03 = p0[768];
        const float v10 = p1[0],    v11 = p1[256],  v12 = p1[512],  v13 = p1[768];
        a0 += w0 * v00; a1 += w0 * v01; a2 += w0 * v02; a3 += w0 * v03;
        a0 += w1 * v10; a1 += w1 * v11; a2 += w1 * v12; a3 += w1 * v13;
    }
    if (k < len) {
        const int2 e = cv[k];
        const float w = __int_as_float(e.y);
        const float* p = g_xT + (size_t)e.x * (NBT * FEAT) + off;
        a0 += w * p[0]; a1 += w * p[256]; a2 += w * p[512]; a3 += w * p[768];
    }

    const float A = g_bnA[f];
    const float C = g_bnC[f] * wsum;
    g_ya[((size_t)(bt0 +  0) * N_NODES + m) * FEAT + f] = A * a0 + C;
    g_ya[((size_t)(bt0 +  8) * N_NODES + m) * FEAT + f] = A * a1 + C;
    g_ya[((size_t)(bt0 + 16) * N_NODES + m) * FEAT + f] = A * a2 + C;
    g_ya[((size_t)(bt0 + 24) * N_NODES + m) * FEAT + f] = A * a3 + C;
}

// ============================================================
// Kernel 5: GRU scan via mma.sync tf32 (3-pass error split)
// block = 64 nodes x 1 batch, 256 threads (8 warps: mw in {0,1}, nw in 0..3)
// A = [ya(K0..31) | h(K32..95)], fragment-major in smem (hi/lo split)
// B = [Wcomb; Whh] (96 x 192), fragment-major in smem (hi/lo split)
// D1 = ya@Wcomb, D2 = h@Whh in separate register accumulators
// ============================================================
#define GEMM_K8(K8, ACC)                                                        \
    {                                                                            \
        const uint4 ah0 = *(const uint4*)&sAH[(((K8)*4 + mw2    )*32 + lane)*4]; \
        const uint4 ah1 = *(const uint4*)&sAH[(((K8)*4 + mw2 + 1)*32 + lane)*4]; \
        const uint4 al0 = *(const uint4*)&sAL[(((K8)*4 + mw2    )*32 + lane)*4]; \
        const uint4 al1 = *(const uint4*)&sAL[(((K8)*4 + mw2 + 1)*32 + lane)*4]; \
        _Pragma("unroll")                                                        \
        for (int nt = 0; nt < 6; ++nt) {                                         \
            const int n8 = nb + nt;                                              \
            const uint2 bh = *(const uint2*)&sBH[(((K8)*24 + n8)*32 + lane)*2];  \
            const uint2 bl = *(const uint2*)&sBL[(((K8)*24 + n8)*32 + lane)*2];  \
            mma8(ACC[0][nt], ah0, bh);                                           \
            mma8(ACC[1][nt], ah1, bh);                                           \
            mma8(ACC[0][nt], al0, bh);                                           \
            mma8(ACC[1][nt], al1, bh);                                           \
            mma8(ACC[0][nt], ah0, bl);                                           \
            mma8(ACC[1][nt], ah1, bl);                                           \
        }                                                                        \
    }

__global__ void __launch_bounds__(GT, 1)
gru_mma_kernel(const float* __restrict__ Whh,
               const float* __restrict__ bhh,
               const float* __restrict__ Wd,
               const float* __restrict__ bd,
               float* __restrict__ out)
{
    extern __shared__ float sm[];
    float* sAH   = sm + O_AH;
    float* sAL   = sm + O_AL;
    float* sBH   = sm + O_BH;
    float* sBL   = sm + O_BL;
    float* sDs   = sm + O_DS;
    float* sBias = sm + O_BIAS;
    float* sWd   = sm + O_WD;

    const int tid  = threadIdx.x;
    const int wid  = tid >> 5;
    const int lane = tid & 31;
    const int mw   = wid & 1;
    const int nw   = wid >> 1;
    const int mw2  = mw * 2;
    const int nb   = nw * 6;

    const int b   = blockIdx.x >> 6;
    const int gm0 = (blockIdx.x & 63) * NP;

    // ---- zero A fragments (h0 = 0; ya region overwritten per t) ----
    for (int i = tid; i < 6144; i += GT) { sAH[i] = 0.0f; sAL[i] = 0.0f; }

    // ---- stage B fragments (hi/lo split), fragment-major ----
    for (int idx = tid; idx < 96 * G3; idx += GT) {
        const int k = idx / G3, n = idx % G3;
        const float w = (k < 32) ? g_Wcomb[k * G3 + n] : Whh[(k - 32) * G3 + n];
        uint32_t hi, lo;
        tf32_split(w, hi, lo);
        const int off = (((k >> 3) * 24 + (n >> 3)) * 32 + ((n & 7) * 4 + (k & 3))) * 2
                        + (((k & 7) >= 4) ? 1 : 0);
        sBH[off] = __uint_as_float(hi);
        sBL[off] = __uint_as_float(lo);
    }
    if (tid < HDIM) {
        sBias[tid]       = g_bcomb[tid]       + bhh[tid];
        sBias[64 + tid]  = g_bcomb[64 + tid]  + bhh[64 + tid];
        sBias[128 + tid] = g_bcomb[128 + tid];
        sBias[192 + tid] = bhh[128 + tid];
        sWd[tid]         = Wd[tid];
    }
    const float bdv = bd[0];

    // ---- per-thread state ----
    const int nodeS = tid >> 2;           // staging node (0..63)
    const int f0    = (tid & 3) * 8;      // staging feature base
    const int m16S  = nodeS >> 4;
    const int rtS   = nodeS & 15;
    const int slotS = (rtS >= 8) ? 1 : 0;
    const int nr    = tid >> 4;           // epilogue row within 16-node slab
    const int hd0   = (tid & 15) * 4;     // epilogue h-dim base

    float h[4][4];
    #pragma unroll
    for (int q = 0; q < 4; ++q)
        #pragma unroll
        for (int i = 0; i < 4; ++i) h[q][i] = 0.0f;

    // prefetch ya for t=0
    float ya[8];
    {
        const float* p = g_ya + ((size_t)(b * TSTEPS) * N_NODES + gm0 + nodeS) * FEAT + f0;
        *(float4*)(ya)     = *(const float4*)(p);
        *(float4*)(ya + 4) = *(const float4*)(p + 4);
    }
    __syncthreads();

    for (int t = 0; t < TSTEPS; ++t) {
        // ---- stage ya_t fragments (hi/lo) ----
        #pragma unroll
        for (int j = 0; j < 8; ++j) {
            const int f = f0 + j;
            uint32_t hi, lo;
            tf32_split(ya[j], hi, lo);
            const int off = (((f >> 3) * 4 + m16S) * 32 + ((rtS & 7) * 4 + (f & 3))) * 4
                            + (((f & 7) >= 4) ? 2 : 0) + slotS;
            sAH[off] = __uint_as_float(hi);
            sAL[off] = __uint_as_float(lo);
        }
        // prefetch ya_{t+1}
        if (t + 1 < TSTEPS) {
            const float* p = g_ya + ((size_t)(b * TSTEPS + t + 1) * N_NODES + gm0 + nodeS) * FEAT + f0;
            *(float4*)(ya)     = *(const float4*)(p);
            *(float4*)(ya + 4) = *(const float4*)(p + 4);
        }
        __syncthreads();

        // ---- GEMMs: acc1 = ya@Wcomb (k8 0..3), acc2 = h@Whh (k8 4..11) ----
        float acc1[2][6][4], acc2[2][6][4];
        #pragma unroll
        for (int mt = 0; mt < 2; ++mt)
            #pragma unroll
            for (int nt = 0; nt < 6; ++nt)
                #pragma unroll
                for (int s = 0; s < 4; ++s) { acc1[mt][nt][s] = 0.0f; acc2[mt][nt][s] = 0.0f; }

        GEMM_K8(0, acc1) GEMM_K8(1, acc1) GEMM_K8(2, acc1) GEMM_K8(3, acc1)
        GEMM_K8(4, acc2) GEMM_K8(5, acc2) GEMM_K8(6, acc2) GEMM_K8(7, acc2)
        GEMM_K8(8, acc2) GEMM_K8(9, acc2) GEMM_K8(10, acc2) GEMM_K8(11, acc2)

        // ---- 4 quarter-passes: store D slab -> GRU epilogue ----
        #pragma unroll
        for (int tt = 0; tt < 4; ++tt) {
            if (mw == (tt >> 1)) {
                const int mt = tt & 1;
                const int r0 = lane >> 2;
                const int cq = (lane & 3) * 2;
                #pragma unroll
                for (int nt = 0; nt < 6; ++nt) {
                    const int n8 = nb + nt;
                    const int c0 = n8 * 8 + cq;
                    const float* a1 = acc1[mt][nt];
                    const float* a2 = acc2[mt][nt];
                    if (n8 < 16) {   // r,z columns: gi+gh summed
                        *(float2*)&sDs[r0 * DS_STRIDE + c0]       = make_float2(a1[0] + a2[0], a1[1] + a2[1]);
                        *(float2*)&sDs[(r0 + 8) * DS_STRIDE + c0] = make_float2(a1[2] + a2[2], a1[3] + a2[3]);
                    } else {         // n columns: ni at c0, nh at c0+64
                        *(float2*)&sDs[r0 * DS_STRIDE + c0]            = make_float2(a1[0], a1[1]);
                        *(float2*)&sDs[(r0 + 8) * DS_STRIDE + c0]      = make_float2(a1[2], a1[3]);
                        *(float2*)&sDs[r0 * DS_STRIDE + c0 + 64]       = make_float2(a2[0], a2[1]);
                        *(float2*)&sDs[(r0 + 8) * DS_STRIDE + c0 + 64] = make_float2(a2[2], a2[3]);
                    }
                }
            }
            __syncthreads();

            // epilogue: 4 (node, hd) gate-sets per thread
            float hp = 0.0f;
            #pragma unroll
            for (int i = 0; i < 4; ++i) {
                const int hd = hd0 + i;
                const float* dr = sDs + nr * DS_STRIDE;
                const float r  = sigm(dr[hd]       + sBias[hd]);
                const float z  = sigm(dr[64 + hd]  + sBias[64 + hd]);
                const float vi = dr[128 + hd] + sBias[128 + hd];
                const float vh = dr[192 + hd] + sBias[192 + hd];
                const float n  = tanhf(vi + r * vh);
                const float hv = (1.0f - z) * n + z * h[tt][i];
                h[tt][i] = hv;
                hp += hv * sWd[hd];
                // write h into A fragments (k = 32 + hd)
                uint32_t hi, lo;
                tf32_split(hv, hi, lo);
                const int k8h = 4 + (hd >> 3);
                const int off = ((k8h * 4 + tt) * 32 + ((nr & 7) * 4 + (hd & 3))) * 4
                                + (((hd & 7) >= 4) ? 2 : 0) + ((nr >= 8) ? 1 : 0);
                sAH[off] = __uint_as_float(hi);
                sAL[off] = __uint_as_float(lo);
            }
            // dense head: reduce 16 threads per node
            hp += __shfl_down_sync(0xffffffffu, hp, 8, 16);
            hp += __shfl_down_sync(0xffffffffu, hp, 4, 16);
            hp += __shfl_down_sync(0xffffffffu, hp, 2, 16);
            hp += __shfl_down_sync(0xffffffffu, hp, 1, 16);
            if ((tid & 15) == 0)
                out[(size_t)(b * TSTEPS + t) * N_NODES + gm0 + tt * 16 + nr] = hp + bdv;
            __syncthreads();
        }
    }
}

// ============================================================
// launch
// ============================================================
extern "C" void kernel_launch(void* const* d_in, const int* in_sizes, int n_in,
                              void* d_out, int out_size)
{
    const float* x     = (const float*)d_in[0];
    const float* adj   = (const float*)d_in[1];
    const float* gamma = (const float*)d_in[2];
    const float* beta  = (const float*)d_in[3];
    const float* Wgcn  = (const float*)d_in[4];
    const float* bgcn  = (const float*)d_in[5];
    const float* Wih   = (const float*)d_in[6];
    const float* Whh   = (const float*)d_in[7];
    const float* bih   = (const float*)d_in[8];
    const float* bhh   = (const float*)d_in[9];
    const float* Wd    = (const float*)d_in[10];
    const float* bd    = (const float*)d_in[11];
    float* out = (float*)d_out;

    const int smem_bytes = SM_FLOATS * (int)sizeof(float);   // 214784
    cudaFuncSetAttribute(gru_mma_kernel, cudaFuncAttributeMaxDynamicSharedMemorySize, smem_bytes);

    build_ell_kernel<<<N_NODES / 8, 256>>>(adj);
    transpose_bn_kernel<<<N_NODES, 256>>>(x);
    finalize_kernel<<<1, 256>>>(gamma, beta, Wgcn, bgcn, Wih, bih);
    agg_kernel<<<N_NODES, 256>>>();
    gru_mma_kernel<<<BATCH * (N_NODES / NP), GT, smem_bytes>>>(Whh, bhh, Wd, bd, out);
}

// round 6
// speedup vs baseline: 1.2213x; 1.2213x over previous
#include <cuda_runtime.h>
#include <cstdint>

#define N_NODES 4096
#define FEAT    32
#define G3      192
#define HDIM    64
#define BATCH   4
#define TSTEPS  8
#define NBT     (BATCH*TSTEPS)           // 32
#define MAXD    128
#define NROWS   (NBT*N_NODES)            // 131072

// ---- gru mma kernel geometry ----
#define NP      128                       // nodes per block
#define GT      256                       // threads (8 warps = 4 node-groups x 2 hd-halves)

// smem float offsets
#define O_B     0                         // B frags [12 k8][24 tiles][32 lanes][bh0 bh1 bl0 bl1]
#define O_A     36864                     // A frags fp32 [12 k8][8 m16][32 lanes][4 regs]
#define O_BIAS  49152                     // [256] r|z|ni|nh
#define O_WD    49408                     // [64]
#define O_HEAD  49472                     // [256] (H*128 + node)
#define SM_FLOATS 49728                   // 198912 bytes

// -------- static device scratch --------
__device__ int   g_row_len[N_NODES];
__device__ float g_row_wsum[N_NODES];
__device__ int2  g_ell_cv[N_NODES * MAXD];
__device__ float g_bnA[FEAT];
__device__ float g_bnC[FEAT];
__device__ float g_Wcomb[FEAT * G3];
__device__ float g_bcomb[G3];
__device__ float g_partN[N_NODES * 64];
__device__ float g_xT[(size_t)N_NODES * NBT * FEAT];
__device__ float g_ya[(size_t)NROWS * FEAT];

// ============================================================
// helpers
// ============================================================
__device__ __forceinline__ uint32_t tf32_rna(float v) {
    uint32_t b;
    asm("cvt.rna.tf32.f32 %0, %1;" : "=r"(b) : "f"(v));
    return b;
}
__device__ __forceinline__ float sigm(float v) { return __fdividef(1.0f, 1.0f + __expf(-v)); }
__device__ __forceinline__ float tanh_fast(float v) {
    const float e = __expf(-2.0f * v);
    return __fdividef(1.0f - e, 1.0f + e);
}
__device__ __forceinline__ void mma8(float* d, const uint4& a, const uint2& b) {
    asm volatile(
        "mma.sync.aligned.m16n8k8.row.col.f32.tf32.tf32.f32 "
        "{%0,%1,%2,%3}, {%4,%5,%6,%7}, {%8,%9}, {%0,%1,%2,%3};"
        : "+f"(d[0]), "+f"(d[1]), "+f"(d[2]), "+f"(d[3])
        : "r"(a.x), "r"(a.y), "r"(a.z), "r"(a.w), "r"(b.x), "r"(b.y));
}

// A fragment fp32 offset: node m (0..127), k (0..95)
__device__ __forceinline__ int AOFF(int m, int k) {
    return (((k >> 3) * 8 + (m >> 4)) * 32 + (m & 7) * 4 + (k & 3)) * 4
           + (((k & 7) >= 4) ? 2 : 0) + (((m & 15) >= 8) ? 1 : 0);
}

// ============================================================
// Kernel 1: dense adj -> packed ELL (deterministic ballot order)
// ============================================================
__global__ void build_ell_kernel(const float* __restrict__ adj)
{
    const int warp = (blockIdx.x * blockDim.x + threadIdx.x) >> 5;
    const int lane = threadIdx.x & 31;
    const float* row = adj + (size_t)warp * N_NODES;
    const int base = warp * MAXD;
    int cnt = 0; float wsum = 0.f;
    for (int i = 0; i < N_NODES / 32; ++i) {
        const int c = i * 32 + lane;
        const float v = row[c];
        wsum += v;
        const unsigned mask = __ballot_sync(0xffffffffu, v != 0.0f);
        if (v != 0.0f) {
            const int pos = cnt + __popc(mask & ((1u << lane) - 1u));
            if (pos < MAXD) g_ell_cv[base + pos] = make_int2(c, __float_as_int(v));
        }
        cnt += __popc(mask);
    }
    #pragma unroll
    for (int o = 16; o > 0; o >>= 1) wsum += __shfl_xor_sync(0xffffffffu, wsum, o);
    if (lane == 0) {
        g_row_len[warp]  = cnt < MAXD ? cnt : MAXD;
        g_row_wsum[warp] = wsum;
    }
}

// ============================================================
// Kernel 2: transpose x + per-node BN partials
// ============================================================
__global__ void __launch_bounds__(256)
transpose_bn_kernel(const float* __restrict__ x)
{
    const int n   = blockIdx.x;
    const int tid = threadIdx.x;
    const int bt  = tid >> 3;
    const int f0  = (tid & 7) * 4;
    const int lane = tid & 31;
    const int w    = tid >> 5;

    const float4 v = *(const float4*)(x + ((size_t)bt * N_NODES + n) * FEAT + f0);
    *(float4*)(g_xT + (size_t)n * (NBT * FEAT) + bt * FEAT + f0) = v;

    float s0 = v.x, s1 = v.y, s2 = v.z, s3 = v.w;
    float q0 = v.x * v.x, q1 = v.y * v.y, q2 = v.z * v.z, q3 = v.w * v.w;
    #pragma unroll
    for (int o = 8; o <= 16; o <<= 1) {
        s0 += __shfl_xor_sync(0xffffffffu, s0, o);
        s1 += __shfl_xor_sync(0xffffffffu, s1, o);
        s2 += __shfl_xor_sync(0xffffffffu, s2, o);
        s3 += __shfl_xor_sync(0xffffffffu, s3, o);
        q0 += __shfl_xor_sync(0xffffffffu, q0, o);
        q1 += __shfl_xor_sync(0xffffffffu, q1, o);
        q2 += __shfl_xor_sync(0xffffffffu, q2, o);
        q3 += __shfl_xor_sync(0xffffffffu, q3, o);
    }
    __shared__ float sh[8][64];
    if (lane < 8) {
        sh[w][f0 + 0]      = s0;  sh[w][f0 + 1]      = s1;
        sh[w][f0 + 2]      = s2;  sh[w][f0 + 3]      = s3;
        sh[w][32 + f0 + 0] = q0;  sh[w][32 + f0 + 1] = q1;
        sh[w][32 + f0 + 2] = q2;  sh[w][32 + f0 + 3] = q3;
    }
    __syncthreads();
    if (tid < 64) {
        float a = 0.f;
        #pragma unroll
        for (int i = 0; i < 8; ++i) a += sh[i][tid];
        g_partN[n * 64 + tid] = a;
    }
}

// ============================================================
// Kernel 3: finalize BN affine + Wcomb/bcomb
// ============================================================
__global__ void __launch_bounds__(256)
finalize_kernel(const float* __restrict__ gamma,
                const float* __restrict__ beta,
                const float* __restrict__ Wgcn,
                const float* __restrict__ bgcn,
                const float* __restrict__ Wih,
                const float* __restrict__ bih)
{
    __shared__ float red[4][64];
    __shared__ float s_sum[32], s_sq[32];
    const int tid = threadIdx.x;
    {
        float a = 0.f;
        const int c = tid & 63;
        for (int n = tid >> 6; n < N_NODES; n += 4) a += g_partN[n * 64 + c];
        red[tid >> 6][c] = a;
    }
    __syncthreads();
    if (tid < 64) {
        const float a = red[0][tid] + red[1][tid] + red[2][tid] + red[3][tid];
        if (tid < 32) s_sum[tid] = a; else s_sq[tid - 32] = a;
    }
    __syncthreads();
    if (tid < 32) {
        const float M    = (float)NROWS;
        const float mean = s_sum[tid] / M;
        const float var  = s_sq[tid] / M - mean * mean;
        const float aK   = gamma[tid] * (1.0f / sqrtf(var + 1e-5f));
        g_bnA[tid] = aK;
        g_bnC[tid] = beta[tid] - mean * aK;
    }
    for (int idx = tid; idx < FEAT * G3; idx += blockDim.x) {
        const int f = idx / G3, j = idx % G3;
        float acc = 0.f;
        #pragma unroll 8
        for (int c = 0; c < 32; ++c) acc += Wgcn[f * 32 + c] * Wih[c * G3 + j];
        g_Wcomb[idx] = acc;
    }
    if (tid < G3) {
        float acc = bih[tid];
        #pragma unroll 8
        for (int c = 0; c < 32; ++c) acc += bgcn[c] * Wih[c * G3 + tid];
        g_bcomb[tid] = acc;
    }
}

// ============================================================
// Kernel 4: aggregation (one block = one node, all 32 bt)
// ============================================================
__global__ void __launch_bounds__(256)
agg_kernel()
{
    const int m   = blockIdx.x;
    const int tid = threadIdx.x;
    const int f   = tid & 31;
    const int bt0 = tid >> 5;

    const int len = g_row_len[m];
    const float wsum = g_row_wsum[m];
    const int2* cv = g_ell_cv + m * MAXD;

    float a0 = 0.f, a1 = 0.f, a2 = 0.f, a3 = 0.f;
    const int off = bt0 * FEAT + f;

    int k = 0;
    for (; k + 1 < len; k += 2) {
        const int2 e0 = cv[k], e1 = cv[k + 1];
        const float w0 = __int_as_float(e0.y), w1 = __int_as_float(e1.y);
        const float* p0 = g_xT + (size_t)e0.x * (NBT * FEAT) + off;
        const float* p1 = g_xT + (size_t)e1.x * (NBT * FEAT) + off;
        const float v00 = p0[0],    v01 = p0[256],  v02 = p0[512],  v03 = p0[768];
        const float v10 = p1[0],    v11 = p1[256],  v12 = p1[512],  v13 = p1[768];
        a0 += w0 * v00; a1 += w0 * v01; a2 += w0 * v02; a3 += w0 * v03;
        a0 += w1 * v10; a1 += w1 * v11; a2 += w1 * v12; a3 += w1 * v13;
    }
    if (k < len) {
        const int2 e = cv[k];
        const float w = __int_as_float(e.y);
        const float* p = g_xT + (size_t)e.x * (NBT * FEAT) + off;
        a0 += w * p[0]; a1 += w * p[256]; a2 += w * p[512]; a3 += w * p[768];
    }

    const float A = g_bnA[f];
    const float C = g_bnC[f] * wsum;
    g_ya[((size_t)(bt0 +  0) * N_NODES + m) * FEAT + f] = A * a0 + C;
    g_ya[((size_t)(bt0 +  8) * N_NODES + m) * FEAT + f] = A * a1 + C;
    g_ya[((size_t)(bt0 + 16) * N_NODES + m) * FEAT + f] = A * a2 + C;
    g_ya[((size_t)(bt0 + 24) * N_NODES + m) * FEAT + f] = A * a3 + C;
}

// ============================================================
// Kernel 5: GRU scan via mma.sync tf32, register-resident epilogue.
// block = 128 nodes x 1 batch, 256 threads.
// warp = (node-group mw: 2 m16 tiles) x (hd-half H).
// Warp col tiles t=0..11 over its half: 0-3 r, 4-7 z, 8-11 n.
//   accRZ  <- all k8 (gi+gh summed in-MMA)
//   accNi  <- k8 0..3  (ya @ Wcomb_n)
//   accNh  <- k8 4..11 (h  @ Whh_n)
// h state lives in registers across t; gates fully thread-local.
// ============================================================
#define GK8(K8)                                                                     \
{                                                                                   \
    const uint4 a0 = *(const uint4*)&sA[(((K8)*8 + mt0)*32 + lane)*4];              \
    const uint4 a1 = *(const uint4*)&sA[(((K8)*8 + mt0 + 1)*32 + lane)*4];          \
    uint4 ah0, al0, ah1, al1;                                                       \
    ah0.x = tf32_rna(__uint_as_float(a0.x));                                        \
    ah0.y = tf32_rna(__uint_as_float(a0.y));                                        \
    ah0.z = tf32_rna(__uint_as_float(a0.z));                                        \
    ah0.w = tf32_rna(__uint_as_float(a0.w));                                        \
    al0.x = tf32_rna(__uint_as_float(a0.x) - __uint_as_float(ah0.x));               \
    al0.y = tf32_rna(__uint_as_float(a0.y) - __uint_as_float(ah0.y));               \
    al0.z = tf32_rna(__uint_as_float(a0.z) - __uint_as_float(ah0.z));               \
    al0.w = tf32_rna(__uint_as_float(a0.w) - __uint_as_float(ah0.w));               \
    ah1.x = tf32_rna(__uint_as_float(a1.x));                                        \
    ah1.y = tf32_rna(__uint_as_float(a1.y));                                        \
    ah1.z = tf32_rna(__uint_as_float(a1.z));                                        \
    ah1.w = tf32_rna(__uint_as_float(a1.w));                                        \
    al1.x = tf32_rna(__uint_as_float(a1.x) - __uint_as_float(ah1.x));               \
    al1.y = tf32_rna(__uint_as_float(a1.y) - __uint_as_float(ah1.y));               \
    al1.z = tf32_rna(__uint_as_float(a1.z) - __uint_as_float(ah1.z));               \
    al1.w = tf32_rna(__uint_as_float(a1.w) - __uint_as_float(ah1.w));               \
    _Pragma("unroll")                                                               \
    for (int t = 0; t < 12; ++t) {                                                  \
        const uint4 bq = *(const uint4*)&sB[(((K8)*24 + Ht + t)*32 + lane)*4];      \
        const uint2 bh = make_uint2(bq.x, bq.y);                                    \
        const uint2 bl = make_uint2(bq.z, bq.w);                                    \
        float* c0p; float* c1p;                                                     \
        if (t < 8)          { c0p = accRZ[0][t];     c1p = accRZ[1][t];     }       \
        else if ((K8) < 4)  { c0p = accNi[0][t - 8]; c1p = accNi[1][t - 8]; }       \
        else                { c0p = accNh[0][t - 8]; c1p = accNh[1][t - 8]; }       \
        mma8(c0p, ah0, bh); mma8(c0p, al0, bh); mma8(c0p, ah0, bl);                 \
        mma8(c1p, ah1, bh); mma8(c1p, al1, bh); mma8(c1p, ah1, bl);                 \
    }                                                                               \
}

__global__ void __launch_bounds__(GT, 1)
gru_mma_kernel(const float* __restrict__ Whh,
               const float* __restrict__ bhh,
               const float* __restrict__ Wd,
               const float* __restrict__ bd,
               float* __restrict__ out)
{
    extern __shared__ float sm[];
    float* sB    = sm + O_B;
    float* sA    = sm + O_A;
    float* sBias = sm + O_BIAS;
    float* sWd   = sm + O_WD;
    float* sHead = sm + O_HEAD;

    const int tid  = threadIdx.x;
    const int wid  = tid >> 5;
    const int lane = tid & 31;
    const int mw   = wid >> 1;          // node group 0..3
    const int H    = wid & 1;           // hd half
    const int mt0  = mw * 2;            // first m16 tile
    const int Ht   = H * 12;            // B tile base

    const int b   = blockIdx.x >> 5;
    const int gm0 = (blockIdx.x & 31) * NP;

    // ---- zero A fragment region (h0 = 0; ya region rewritten per t) ----
    for (int i = tid; i < 12288; i += GT) sA[i] = 0.0f;

    // ---- stage B fragments: permuted cols, tf32 hi/lo interleaved ----
    for (int idx = tid; idx < 96 * G3; idx += GT) {
        const int k = idx / G3, n = idx % G3;
        const float w = (k < 32) ? g_Wcomb[k * G3 + n] : Whh[(k - 32) * G3 + n];
        const uint32_t hi = tf32_rna(w);
        const uint32_t lo = tf32_rna(w - __uint_as_float(hi));
        const int g   = n >> 6;
        const int hd  = n & 63;
        const int Hh  = hd >> 5;
        const int hdl = hd & 31;
        const int t   = g * 4 + (hdl >> 3);
        const int c   = hdl & 7;
        const int base = (((k >> 3) * 24 + Hh * 12 + t) * 32 + c * 4 + (k & 3)) * 4
                         + (((k & 7) >= 4) ? 1 : 0);
        sB[base]     = __uint_as_float(hi);
        sB[base + 2] = __uint_as_float(lo);
    }
    if (tid < HDIM) {
        sBias[tid]       = g_bcomb[tid]       + bhh[tid];        // r
        sBias[64 + tid]  = g_bcomb[64 + tid]  + bhh[64 + tid];   // z
        sBias[128 + tid] = g_bcomb[128 + tid];                   // n_i
        sBias[192 + tid] = bhh[128 + tid];                       // n_h
        sWd[tid]         = Wd[tid];
    }
    const float bdv = bd[0];

    // ---- per-thread epilogue geometry ----
    const int gr = lane >> 2;
    const int c0 = (lane & 3) * 2;

    float hprev[2][4][4];
    #pragma unroll
    for (int mi = 0; mi < 2; ++mi)
        #pragma unroll
        for (int t = 0; t < 4; ++t)
            #pragma unroll
            for (int s = 0; s < 4; ++s) hprev[mi][t][s] = 0.0f;

    // ---- ya staging geometry + prefetch t=0 ----
    const int nodeS = tid >> 1;
    const int f0s   = (tid & 1) * 16;
    float4 pf[4];
    {
        const float* p = g_ya + ((size_t)(b * TSTEPS) * N_NODES + gm0 + nodeS) * FEAT + f0s;
        pf[0] = *(const float4*)(p);      pf[1] = *(const float4*)(p + 4);
        pf[2] = *(const float4*)(p + 8);  pf[3] = *(const float4*)(p + 12);
    }

    __syncthreads();

    for (int t8 = 0; t8 < TSTEPS; ++t8) {
        // ---- stage ya_t fragments (fp32) ----
        #pragma unroll
        for (int q = 0; q < 4; ++q) {
            const float* v = (const float*)&pf[q];
            #pragma unroll
            for (int j = 0; j < 4; ++j) {
                const int f = f0s + q * 4 + j;
                sA[AOFF(nodeS, f)] = v[j];
            }
        }
        __syncthreads();

        // ---- accumulators ----
        float accRZ[2][8][4], accNi[2][4][4], accNh[2][4][4];
        #pragma unroll
        for (int mi = 0; mi < 2; ++mi) {
            #pragma unroll
            for (int t = 0; t < 8; ++t)
                #pragma unroll
                for (int s = 0; s < 4; ++s) accRZ[mi][t][s] = 0.0f;
            #pragma unroll
            for (int t = 0; t < 4; ++t)
                #pragma unroll
                for (int s = 0; s < 4; ++s) { accNi[mi][t][s] = 0.0f; accNh[mi][t][s] = 0.0f; }
        }

        GK8(0) GK8(1) GK8(2) GK8(3) GK8(4) GK8(5)
        GK8(6) GK8(7) GK8(8) GK8(9) GK8(10) GK8(11)

        // prefetch next ya
        if (t8 + 1 < TSTEPS) {
            const float* p = g_ya + ((size_t)(b * TSTEPS + t8 + 1) * N_NODES + gm0 + nodeS) * FEAT + f0s;
            pf[0] = *(const float4*)(p);      pf[1] = *(const float4*)(p + 4);
            pf[2] = *(const float4*)(p + 8);  pf[3] = *(const float4*)(p + 12);
        }
        __syncthreads();   // all warps done reading A frags (ya + h_prev)

        // ---- register epilogue: gates + h update + head partial + h frag STS ----
        float hp[2][2] = {{0.f, 0.f}, {0.f, 0.f}};
        #pragma unroll
        for (int mi = 0; mi < 2; ++mi) {
            const int m16 = mt0 + mi;
            #pragma unroll
            for (int t = 0; t < 4; ++t) {
                #pragma unroll
                for (int s = 0; s < 4; ++s) {
                    const int cc = c0 + (s & 1);
                    const int hd = H * 32 + t * 8 + cc;
                    const float r = sigm(accRZ[mi][t][s]     + sBias[hd]);
                    const float z = sigm(accRZ[mi][t + 4][s] + sBias[64 + hd]);
                    const float n = tanh_fast(accNi[mi][t][s] + sBias[128 + hd]
                                              + r * (accNh[mi][t][s] + sBias[192 + hd]));
                    const float hv = (1.0f - z) * n + z * hprev[mi][t][s];
                    hprev[mi][t][s] = hv;
                    hp[mi][s >> 1] += hv * sWd[hd];
                    // write h into A fragments at k = 32 + hd
                    const int off = (((4 + H * 4 + t) * 8 + m16) * 32 + gr * 4 + (cc & 3)) * 4
                                    + ((cc >= 4) ? 2 : 0) + (s >> 1);
                    sA[off] = hv;
                }
            }
        }
        // head reduce across the 4 lanes sharing gr
        #pragma unroll
        for (int mi = 0; mi < 2; ++mi)
            #pragma unroll
            for (int rh = 0; rh < 2; ++rh) {
                float v = hp[mi][rh];
                v += __shfl_xor_sync(0xffffffffu, v, 1);
                v += __shfl_xor_sync(0xffffffffu, v, 2);
                hp[mi][rh] = v;
            }
        if ((lane & 3) == 0) {
            #pragma unroll
            for (int mi = 0; mi < 2; ++mi) {
                const int mbase = (mt0 + mi) * 16 + gr;
                sHead[H * 128 + mbase]     = hp[mi][0];
                sHead[H * 128 + mbase + 8] = hp[mi][1];
            }
        }
        __syncthreads();   // h frags + sHead complete

        if (tid < NP) {
            out[(size_t)(b * TSTEPS + t8) * N_NODES + gm0 + tid] =
                bdv + sHead[tid] + sHead[128 + tid];
        }
        // next loop's ya staging is disjoint from sHead; A-frag ya region is
        // only re-written after this point and re-read after the next sync.
    }
}

// ============================================================
// launch
// ============================================================
extern "C" void kernel_launch(void* const* d_in, const int* in_sizes, int n_in,
                              void* d_out, int out_size)
{
    const float* x     = (const float*)d_in[0];
    const float* adj   = (const float*)d_in[1];
    const float* gamma = (const float*)d_in[2];
    const float* beta  = (const float*)d_in[3];
    const float* Wgcn  = (const float*)d_in[4];
    const float* bgcn  = (const float*)d_in[5];
    const float* Wih   = (const float*)d_in[6];
    const float* Whh   = (const float*)d_in[7];
    const float* bih   = (const float*)d_in[8];
    const float* bhh   = (const float*)d_in[9];
    const float* Wd    = (const float*)d_in[10];
    const float* bd    = (const float*)d_in[11];
    float* out = (float*)d_out;

    const int smem_bytes = SM_FLOATS * (int)sizeof(float);   // 198912
    cudaFuncSetAttribute(gru_mma_kernel, cudaFuncAttributeMaxDynamicSharedMemorySize, smem_bytes);

    build_ell_kernel<<<N_NODES / 8, 256>>>(adj);
    transpose_bn_kernel<<<N_NODES, 256>>>(x);
    finalize_kernel<<<1, 256>>>(gamma, beta, Wgcn, bgcn, Wih, bih);
    agg_kernel<<<N_NODES, 256>>>();
    gru_mma_kernel<<<BATCH * (N_NODES / NP), GT, smem_bytes>>>(Whh, bhh, Wd, bd, out);
}

// round 7
// speedup vs baseline: 1.5124x; 1.2384x over previous
#include <cuda_runtime.h>
#include <cuda_fp16.h>
#include <cstdint>

#define N_NODES 4096
#define FEAT    32
#define G3      192
#define HDIM    64
#define BATCH   4
#define TSTEPS  8
#define NBT     (BATCH*TSTEPS)           // 32
#define MAXD    128
#define NROWS   (NBT*N_NODES)            // 131072

// ---- gru mma kernel geometry ----
#define NP      64                        // nodes per block
#define GT      256                       // threads (8 warps = 4 m16 x 2 hd-halves)

// smem float offsets
#define O_B     0                         // B frags [6 k16][24 tiles][32 lanes][bh0 bh1 bl0 bl1]
#define O_AH    18432                     // A hi frags [6 k16][4 m16][32 lanes][4]
#define O_AL    21504                     // A lo frags
#define O_BIAS  24576                     // [256] r|z|ni|nh
#define O_WD    24832                     // [64]
#define O_HEAD  24896                     // [128]
#define SM_FLOATS 25024                   // 100096 bytes

// -------- static device scratch --------
__device__ int   g_row_len[N_NODES];
__device__ float g_row_wsum[N_NODES];
__device__ int2  g_ell_cv[N_NODES * MAXD];
__device__ float g_bnA[FEAT];
__device__ float g_bnC[FEAT];
__device__ float g_Wcomb[FEAT * G3];
__device__ float g_bcomb[G3];
__device__ float g_partN[N_NODES * 64];
__device__ float g_xT[(size_t)N_NODES * NBT * FEAT];
__device__ float g_ya[(size_t)NROWS * FEAT];

// ============================================================
// helpers
// ============================================================
__device__ __forceinline__ float sigm(float v) { return __fdividef(1.0f, 1.0f + __expf(-v)); }
__device__ __forceinline__ float tanh_fast(float v) {
    const float e = __expf(-2.0f * v);
    return __fdividef(1.0f - e, 1.0f + e);
}
// pack two floats to f16x2 (lo in low half, hi_val in high half)
__device__ __forceinline__ uint32_t pack_f16x2(float lo_val, float hi_val) {
    uint32_t r;
    asm("cvt.rn.f16x2.f32 %0, %1, %2;" : "=r"(r) : "f"(hi_val), "f"(lo_val));
    return r;
}
__device__ __forceinline__ void mma16(float* d, const uint4& a, const uint2& b) {
    asm volatile(
        "mma.sync.aligned.m16n8k16.row.col.f32.f16.f16.f32 "
        "{%0,%1,%2,%3}, {%4,%5,%6,%7}, {%8,%9}, {%0,%1,%2,%3};"
        : "+f"(d[0]), "+f"(d[1]), "+f"(d[2]), "+f"(d[3])
        : "r"(a.x), "r"(a.y), "r"(a.z), "r"(a.w), "r"(b.x), "r"(b.y));
}

// ============================================================
// Kernel 1: dense adj -> packed ELL (deterministic ballot order)
// ============================================================
__global__ void build_ell_kernel(const float* __restrict__ adj)
{
    const int warp = (blockIdx.x * blockDim.x + threadIdx.x) >> 5;
    const int lane = threadIdx.x & 31;
    const float* row = adj + (size_t)warp * N_NODES;
    const int base = warp * MAXD;
    int cnt = 0; float wsum = 0.f;
    for (int i = 0; i < N_NODES / 32; ++i) {
        const int c = i * 32 + lane;
        const float v = row[c];
        wsum += v;
        const unsigned mask = __ballot_sync(0xffffffffu, v != 0.0f);
        if (v != 0.0f) {
            const int pos = cnt + __popc(mask & ((1u << lane) - 1u));
            if (pos < MAXD) g_ell_cv[base + pos] = make_int2(c, __float_as_int(v));
        }
        cnt += __popc(mask);
    }
    #pragma unroll
    for (int o = 16; o > 0; o >>= 1) wsum += __shfl_xor_sync(0xffffffffu, wsum, o);
    if (lane == 0) {
        g_row_len[warp]  = cnt < MAXD ? cnt : MAXD;
        g_row_wsum[warp] = wsum;
    }
}

// ============================================================
// Kernel 2: transpose x + per-node BN partials
// ============================================================
__global__ void __launch_bounds__(256)
transpose_bn_kernel(const float* __restrict__ x)
{
    const int n   = blockIdx.x;
    const int tid = threadIdx.x;
    const int bt  = tid >> 3;
    const int f0  = (tid & 7) * 4;
    const int lane = tid & 31;
    const int w    = tid >> 5;

    const float4 v = *(const float4*)(x + ((size_t)bt * N_NODES + n) * FEAT + f0);
    *(float4*)(g_xT + (size_t)n * (NBT * FEAT) + bt * FEAT + f0) = v;

    float s0 = v.x, s1 = v.y, s2 = v.z, s3 = v.w;
    float q0 = v.x * v.x, q1 = v.y * v.y, q2 = v.z * v.z, q3 = v.w * v.w;
    #pragma unroll
    for (int o = 8; o <= 16; o <<= 1) {
        s0 += __shfl_xor_sync(0xffffffffu, s0, o);
        s1 += __shfl_xor_sync(0xffffffffu, s1, o);
        s2 += __shfl_xor_sync(0xffffffffu, s2, o);
        s3 += __shfl_xor_sync(0xffffffffu, s3, o);
        q0 += __shfl_xor_sync(0xffffffffu, q0, o);
        q1 += __shfl_xor_sync(0xffffffffu, q1, o);
        q2 += __shfl_xor_sync(0xffffffffu, q2, o);
        q3 += __shfl_xor_sync(0xffffffffu, q3, o);
    }
    __shared__ float sh[8][64];
    if (lane < 8) {
        sh[w][f0 + 0]      = s0;  sh[w][f0 + 1]      = s1;
        sh[w][f0 + 2]      = s2;  sh[w][f0 + 3]      = s3;
        sh[w][32 + f0 + 0] = q0;  sh[w][32 + f0 + 1] = q1;
        sh[w][32 + f0 + 2] = q2;  sh[w][32 + f0 + 3] = q3;
    }
    __syncthreads();
    if (tid < 64) {
        float a = 0.f;
        #pragma unroll
        for (int i = 0; i < 8; ++i) a += sh[i][tid];
        g_partN[n * 64 + tid] = a;
    }
}

// ============================================================
// Kernel 3: finalize BN affine + Wcomb/bcomb
// ============================================================
__global__ void __launch_bounds__(256)
finalize_kernel(const float* __restrict__ gamma,
                const float* __restrict__ beta,
                const float* __restrict__ Wgcn,
                const float* __restrict__ bgcn,
                const float* __restrict__ Wih,
                const float* __restrict__ bih)
{
    __shared__ float red[4][64];
    __shared__ float s_sum[32], s_sq[32];
    const int tid = threadIdx.x;
    {
        float a = 0.f;
        const int c = tid & 63;
        for (int n = tid >> 6; n < N_NODES; n += 4) a += g_partN[n * 64 + c];
        red[tid >> 6][c] = a;
    }
    __syncthreads();
    if (tid < 64) {
        const float a = red[0][tid] + red[1][tid] + red[2][tid] + red[3][tid];
        if (tid < 32) s_sum[tid] = a; else s_sq[tid - 32] = a;
    }
    __syncthreads();
    if (tid < 32) {
        const float M    = (float)NROWS;
        const float mean = s_sum[tid] / M;
        const float var  = s_sq[tid] / M - mean * mean;
        const float aK   = gamma[tid] * (1.0f / sqrtf(var + 1e-5f));
        g_bnA[tid] = aK;
        g_bnC[tid] = beta[tid] - mean * aK;
    }
    for (int idx = tid; idx < FEAT * G3; idx += blockDim.x) {
        const int f = idx / G3, j = idx % G3;
        float acc = 0.f;
        #pragma unroll 8
        for (int c = 0; c < 32; ++c) acc += Wgcn[f * 32 + c] * Wih[c * G3 + j];
        g_Wcomb[idx] = acc;
    }
    if (tid < G3) {
        float acc = bih[tid];
        #pragma unroll 8
        for (int c = 0; c < 32; ++c) acc += bgcn[c] * Wih[c * G3 + tid];
        g_bcomb[tid] = acc;
    }
}

// ============================================================
// Kernel 4: aggregation (one block = one node, all 32 bt)
// ============================================================
__global__ void __launch_bounds__(256)
agg_kernel()
{
    const int m   = blockIdx.x;
    const int tid = threadIdx.x;
    const int f   = tid & 31;
    const int bt0 = tid >> 5;

    const int len = g_row_len[m];
    const float wsum = g_row_wsum[m];
    const int2* cv = g_ell_cv + m * MAXD;

    float a0 = 0.f, a1 = 0.f, a2 = 0.f, a3 = 0.f;
    const int off = bt0 * FEAT + f;

    int k = 0;
    for (; k + 1 < len; k += 2) {
        const int2 e0 = cv[k], e1 = cv[k + 1];
        const float w0 = __int_as_float(e0.y), w1 = __int_as_float(e1.y);
        const float* p0 = g_xT + (size_t)e0.x * (NBT * FEAT) + off;
        const float* p1 = g_xT + (size_t)e1.x * (NBT * FEAT) + off;
        const float v00 = p0[0],    v01 = p0[256],  v02 = p0[512],  v03 = p0[768];
        const float v10 = p1[0],    v11 = p1[256],  v12 = p1[512],  v13 = p1[768];
        a0 += w0 * v00; a1 += w0 * v01; a2 += w0 * v02; a3 += w0 * v03;
        a0 += w1 * v10; a1 += w1 * v11; a2 += w1 * v12; a3 += w1 * v13;
    }
    if (k < len) {
        const int2 e = cv[k];
        const float w = __int_as_float(e.y);
        const float* p = g_xT + (size_t)e.x * (NBT * FEAT) + off;
        a0 += w * p[0]; a1 += w * p[256]; a2 += w * p[512]; a3 += w * p[768];
    }

    const float A = g_bnA[f];
    const float C = g_bnC[f] * wsum;
    g_ya[((size_t)(bt0 +  0) * N_NODES + m) * FEAT + f] = A * a0 + C;
    g_ya[((size_t)(bt0 +  8) * N_NODES + m) * FEAT + f] = A * a1 + C;
    g_ya[((size_t)(bt0 + 16) * N_NODES + m) * FEAT + f] = A * a2 + C;
    g_ya[((size_t)(bt0 + 24) * N_NODES + m) * FEAT + f] = A * a3 + C;
}

// ============================================================
// Kernel 5: GRU scan via mma.sync m16n8k16 fp16 (3-term split).
// block = 64 nodes x 1 batch, 256 threads, 2 blocks/SM, grid 256.
// warp = (m16 tile mw: 0..3) x (hd half H).
// Warp col tiles tt=0..11 over its hd-half: 0-3 r, 4-7 z, 8-11 n.
//   accRZ <- all k16 chunks (gi+gh summed in-MMA)
//   accNi <- chunks 0..1 (ya @ Wcomb_n),  accNh <- chunks 2..5 (h @ Whh_n)
// h state in registers across t; epilogue fully register-resident.
// ============================================================
#define GK16(C, ACCN)                                                            \
{                                                                                \
    const uint4 ah = *(const uint4*)&sAh[(((C) * 4 + mw) * 32 + lane) * 4];      \
    const uint4 al = *(const uint4*)&sAl[(((C) * 4 + mw) * 32 + lane) * 4];      \
    _Pragma("unroll")                                                            \
    for (int tt = 0; tt < 12; ++tt) {                                            \
        const uint4 bq = *(const uint4*)&sB[(((C) * 24 + Ht + tt) * 32 + lane) * 4]; \
        const uint2 bh = make_uint2(bq.x, bq.y);                                 \
        const uint2 bl = make_uint2(bq.z, bq.w);                                 \
        float* cp = (tt < 8) ? accRZ[tt] : ACCN[tt - 8];                         \
        mma16(cp, ah, bh);                                                       \
        mma16(cp, al, bh);                                                       \
        mma16(cp, ah, bl);                                                       \
    }                                                                            \
}

__global__ void __launch_bounds__(GT, 2)
gru_mma_kernel(const float* __restrict__ Whh,
               const float* __restrict__ bhh,
               const float* __restrict__ Wd,
               const float* __restrict__ bd,
               float* __restrict__ out)
{
    extern __shared__ float sm[];
    float* sB    = sm + O_B;
    float* sAh   = sm + O_AH;
    float* sAl   = sm + O_AL;
    float* sBias = sm + O_BIAS;
    float* sWd   = sm + O_WD;
    float* sHead = sm + O_HEAD;

    const int tid  = threadIdx.x;
    const int wid  = tid >> 5;
    const int lane = tid & 31;
    const int mw   = wid >> 1;          // m16 tile 0..3
    const int H    = wid & 1;           // hd half
    const int Ht   = H * 12;            // B tile base

    const int b   = blockIdx.x >> 6;
    const int gm0 = (blockIdx.x & 63) * NP;

    // ---- zero A fragment regions (h0 = 0) ----
    for (int i = tid; i < 3072; i += GT) { sAh[i] = 0.0f; sAl[i] = 0.0f; }

    // ---- stage B fragments (fp16 hi/lo, permuted cols) ----
    {
        __half* pB = (__half*)sB;
        for (int idx = tid; idx < 96 * G3; idx += GT) {
            const int k = idx / G3, n = idx % G3;
            const float w = (k < 32) ? g_Wcomb[k * G3 + n] : Whh[(k - 32) * G3 + n];
            const __half hh = __float2half_rn(w);
            const __half hl = __float2half_rn(w - __half2float(hh));
            const int g    = n >> 6;
            const int hd   = n & 63;
            const int Hh   = hd >> 5;
            const int hdl  = hd & 31;
            const int tile = Hh * 12 + g * 4 + (hdl >> 3);
            const int ccol = hdl & 7;
            const int chunk = k >> 4;
            const int rem   = k & 15;
            const int lt    = ccol * 4 + ((rem & 7) >> 1);
            const int regB  = (rem >= 8) ? 1 : 0;
            const int hb    = rem & 1;
            const int base  = ((chunk * 24 + tile) * 32 + lt) * 4;
            pB[(base + regB) * 2 + hb]     = hh;
            pB[(base + 2 + regB) * 2 + hb] = hl;
        }
    }
    if (tid < HDIM) {
        sBias[tid]       = g_bcomb[tid]       + bhh[tid];        // r
        sBias[64 + tid]  = g_bcomb[64 + tid]  + bhh[64 + tid];   // z
        sBias[128 + tid] = g_bcomb[128 + tid];                   // n_i
        sBias[192 + tid] = bhh[128 + tid];                       // n_h
        sWd[tid]         = Wd[tid];
    }
    const float bdv = bd[0];

    // ---- epilogue geometry ----
    const int gr = lane >> 2;
    const int c0 = (lane & 3) * 2;

    float hprev[4][4];
    #pragma unroll
    for (int t = 0; t < 4; ++t)
        #pragma unroll
        for (int s = 0; s < 4; ++s) hprev[t][s] = 0.0f;

    // ---- ya staging geometry + prefetch t=0 ----
    const int nodeS = tid >> 2;           // 0..63
    const int fc    = tid & 3;            // feature chunk: f base = fc*8
    const int baseS = (((fc >> 1) * 4 + (nodeS >> 4)) * 32 + (nodeS & 7) * 4) * 4
                      + ((fc & 1) ? 2 : 0) + (((nodeS & 15) >= 8) ? 1 : 0);
    float4 pf0, pf1;
    {
        const float* p = g_ya + ((size_t)(b * TSTEPS) * N_NODES + gm0 + nodeS) * FEAT + fc * 8;
        pf0 = *(const float4*)(p);
        pf1 = *(const float4*)(p + 4);
    }

    __syncthreads();

    for (int t8 = 0; t8 < TSTEPS; ++t8) {
        // ---- stage ya_t fragments (fp16 hi/lo) ----
        {
            float v[8];
            *(float4*)(v) = pf0; *(float4*)(v + 4) = pf1;
            #pragma unroll
            for (int j = 0; j < 4; ++j) {
                const float a = v[2 * j], bvv = v[2 * j + 1];
                const __half ha = __float2half_rn(a);
                const __half hb = __float2half_rn(bvv);
                const uint32_t wh = pack_f16x2(__half2float(ha) * 0.0f + a, bvv); // placeholder avoided below
                (void)wh;
                const uint32_t whi = pack_f16x2(a, bvv);
                const float ra = a - __half2float(ha);
                const float rb = bvv - __half2float(hb);
                const uint32_t wlo = pack_f16x2(ra, rb);
                sAh[baseS + j * 4] = __uint_as_float(whi);
                sAl[baseS + j * 4] = __uint_as_float(wlo);
            }
        }
        __syncthreads();

        // ---- accumulators ----
        float accRZ[8][4], accNi[4][4], accNh[4][4];
        #pragma unroll
        for (int t = 0; t < 8; ++t)
            #pragma unroll
            for (int s = 0; s < 4; ++s) accRZ[t][s] = 0.0f;
        #pragma unroll
        for (int t = 0; t < 4; ++t)
            #pragma unroll
            for (int s = 0; s < 4; ++s) { accNi[t][s] = 0.0f; accNh[t][s] = 0.0f; }

        GK16(0, accNi) GK16(1, accNi)
        GK16(2, accNh) GK16(3, accNh) GK16(4, accNh) GK16(5, accNh)

        // prefetch next ya
        if (t8 + 1 < TSTEPS) {
            const float* p = g_ya + ((size_t)(b * TSTEPS + t8 + 1) * N_NODES + gm0 + nodeS) * FEAT + fc * 8;
            pf0 = *(const float4*)(p);
            pf1 = *(const float4*)(p + 4);
        }
        __syncthreads();   // all warps done reading A frags

        // ---- register epilogue ----
        float hp0 = 0.0f, hp1 = 0.0f;
        #pragma unroll
        for (int t = 0; t < 4; ++t) {
            float hv[4];
            #pragma unroll
            for (int s = 0; s < 4; ++s) {
                const int cc = c0 + (s & 1);
                const int hd = H * 32 + t * 8 + cc;
                const float r = sigm(accRZ[t][s]     + sBias[hd]);
                const float z = sigm(accRZ[t + 4][s] + sBias[64 + hd]);
                const float n = tanh_fast(accNi[t][s] + sBias[128 + hd]
                                          + r * (accNh[t][s] + sBias[192 + hd]));
                hv[s] = (1.0f - z) * n + z * hprev[t][s];
                hprev[t][s] = hv[s];
            }
            hp0 += hv[0] * sWd[H * 32 + t * 8 + c0] + hv[1] * sWd[H * 32 + t * 8 + c0 + 1];
            hp1 += hv[2] * sWd[H * 32 + t * 8 + c0] + hv[3] * sWd[H * 32 + t * 8 + c0 + 1];
            // write h back into A fragments at k = 32 + H*32 + t*8 + cc
            const int chunk = 2 + H * 2 + (t >> 1);
            const int reg2  = (t & 1) * 2;
            const int base  = ((chunk * 4 + mw) * 32 + lane) * 4;
            const __half h0 = __float2half_rn(hv[0]);
            const __half h1 = __float2half_rn(hv[1]);
            const __half h2 = __float2half_rn(hv[2]);
            const __half h3 = __float2half_rn(hv[3]);
            sAh[base + reg2]     = __uint_as_float(pack_f16x2(hv[0], hv[1]));
            sAh[base + reg2 + 1] = __uint_as_float(pack_f16x2(hv[2], hv[3]));
            sAl[base + reg2]     = __uint_as_float(pack_f16x2(hv[0] - __half2float(h0),
                                                              hv[1] - __half2float(h1)));
            sAl[base + reg2 + 1] = __uint_as_float(pack_f16x2(hv[2] - __half2float(h2),
                                                              hv[3] - __half2float(h3)));
        }
        // head reduce across the 4 lanes sharing gr
        hp0 += __shfl_xor_sync(0xffffffffu, hp0, 1);
        hp0 += __shfl_xor_sync(0xffffffffu, hp0, 2);
        hp1 += __shfl_xor_sync(0xffffffffu, hp1, 1);
        hp1 += __shfl_xor_sync(0xffffffffu, hp1, 2);
        if ((lane & 3) == 0) {
            sHead[H * 64 + mw * 16 + gr]     = hp0;
            sHead[H * 64 + mw * 16 + gr + 8] = hp1;
        }
        __syncthreads();   // h frags + sHead complete

        if (tid < NP) {
            out[(size_t)(b * TSTEPS + t8) * N_NODES + gm0 + tid] =
                bdv + sHead[tid] + sHead[64 + tid];
        }
    }
}

// ============================================================
// launch
// ============================================================
extern "C" void kernel_launch(void* const* d_in, const int* in_sizes, int n_in,
                              void* d_out, int out_size)
{
    const float* x     = (const float*)d_in[0];
    const float* adj   = (const float*)d_in[1];
    const float* gamma = (const float*)d_in[2];
    const float* beta  = (const float*)d_in[3];
    const float* Wgcn  = (const float*)d_in[4];
    const float* bgcn  = (const float*)d_in[5];
    const float* Wih   = (const float*)d_in[6];
    const float* Whh   = (const float*)d_in[7];
    const float* bih   = (const float*)d_in[8];
    const float* bhh   = (const float*)d_in[9];
    const float* Wd    = (const float*)d_in[10];
    const float* bd    = (const float*)d_in[11];
    float* out = (float*)d_out;

    const int smem_bytes = SM_FLOATS * (int)sizeof(float);   // 100096
    cudaFuncSetAttribute(gru_mma_kernel, cudaFuncAttributeMaxDynamicSharedMemorySize, smem_bytes);

    build_ell_kernel<<<N_NODES / 8, 256>>>(adj);
    transpose_bn_kernel<<<N_NODES, 256>>>(x);
    finalize_kernel<<<1, 256>>>(gamma, beta, Wgcn, bgcn, Wih, bih);
    agg_kernel<<<N_NODES, 256>>>();
    gru_mma_kernel<<<BATCH * (N_NODES / NP), GT, smem_bytes>>>(Whh, bhh, Wd, bd, out);
}